// round 12
// baseline (speedup 1.0000x reference)
#include <cuda_runtime.h>

#define BSZ 16
#define SR 16
#define IMW 2048
#define IMH 2048
#define NBX (IMW/BSZ)   // 128
#define NBY (IMH/BSZ)   // 128

#define BPC 2                   // image blocks per CTA (horizontal)
#define WINW (BPC*BSZ + 2*SR)   // 64
#define WINH (BSZ + 2*SR)       // 48
#define RST 66                  // ref row stride in pairs: 528 B -> conflict-free
#define NTHREADS 352            // 11 warps
#define J8END 264               // items [0,264): 2 blocks x 4 groups x 33 dy, NJ=8
#define NITEMS 330              // + 66 j1 items (dx=32): [264,330)

typedef unsigned long long ull;

__device__ __forceinline__ ull f2x_add(ull a, ull b) {
    ull d; asm("add.rn.f32x2 %0, %1, %2;" : "=l"(d) : "l"(a), "l"(b)); return d;
}
__device__ __forceinline__ ull umin64(ull a, ull b) { return b < a ? b : a; }

// acc += pack(min(a.lo,b.lo), min(a.hi,b.hi)); movs fold to register-pair naming
__device__ __forceinline__ ull f2x_minadd(ull acc, ull a, ull b) {
    float alo, ahi, blo, bhi;
    asm("mov.b64 {%0,%1}, %2;" : "=f"(alo), "=f"(ahi) : "l"(a));
    asm("mov.b64 {%0,%1}, %2;" : "=f"(blo), "=f"(bhi) : "l"(b));
    float m0 = fminf(alo, blo);
    float m1 = fminf(ahi, bhi);
    ull m; asm("mov.b64 %0, {%1,%2};" : "=l"(m) : "f"(m0), "f"(m1));
    return f2x_add(acc, m);
}

__global__ __launch_bounds__(NTHREADS, 3)
void me_sad_kernel(const float* __restrict__ cur,
                   const float* __restrict__ refF,
                   float* __restrict__ out)
{
    __shared__ __align__(16) ull s_ref[47 * RST];          // 24.8 KB row-pair window
    __shared__ __align__(16) ull s_cur[BPC * 8 * 16];      // 2 KB
    __shared__ ull s_red[NTHREADS];                        // 2.8 KB
    __shared__ float s_h[BPC * 48 * 33];                   // 12.7 KB: H sums, then C in place
    __shared__ double s_scd[BPC];

    const int t  = threadIdx.x;
    const int cx = blockIdx.x;          // 0..63
    const int by = blockIdx.y;          // 0..127
    const int gx0 = cx * (BPC * BSZ) - SR;
    const int gy0 = by * BSZ - SR;

    // ---- fill ref window (64x48): value feeds .lo of pair-row p and .hi of pair-row p-1
    float* fref = reinterpret_cast<float*>(s_ref);
    for (int i = t; i < WINW * WINH; i += NTHREADS) {
        int pr = i / WINW, pc = i - pr * WINW;
        int gy = gy0 + pr, gx = gx0 + pc;
        float v = 0.0f;
        if ((unsigned)gy < (unsigned)IMH && (unsigned)gx < (unsigned)IMW)
            v = refF[gy * IMW + gx];
        if (pr < WINH - 1) fref[(pr * RST + pc) * 2]           = v;
        if (pr >= 1)       fref[((pr - 1) * RST + pc) * 2 + 1] = v;
    }
    // ---- fill current blocks (2 x 16x16) as row-pairs
    float* fcur = reinterpret_cast<float*>(s_cur);
    for (int i = t; i < BPC * 256; i += NTHREADS) {
        int b = i >> 8;
        int r = (i >> 4) & 15, c = i & 15;
        float v = cur[(by * BSZ + r) * IMW + (cx * BPC + b) * BSZ + c];
        fcur[(b * 128 + (r >> 1) * 16 + c) * 2 + (r & 1)] = v;
    }
    __syncthreads();

    // ---- H phase: horizontal 16-wide sliding sums of ref rows (fp64), per (block, row)
    if (t < 96) {
        const int b = t / 48, y = t - b * 48;
        // raw ref value at (y,col): row y is .lo of pair y (y<47) or .hi of pair 46 (y==47)
        const float* rowp = (y < 47) ? (fref + y * RST * 2) : (fref + 46 * RST * 2 + 1);
        const int col0 = b * BSZ;
        double s = 0.0;
        #pragma unroll
        for (int c = 0; c < 16; c++) s += (double)rowp[(col0 + c) * 2];
        float* hrow = s_h + (b * 48 + y) * 33;
        hrow[0] = (float)s;
        for (int dx = 1; dx <= 32; dx++) {
            s += (double)rowp[(col0 + dx + 15) * 2] - (double)rowp[(col0 + dx - 1) * 2];
            hrow[dx] = (float)s;
        }
    } else if (t < 160) {
        // ---- S_c: per-block sum of current block (fp64, warp-parallel)
        const int b = (t - 96) >> 5, l = (t - 96) & 31;
        const float* fc = fcur + b * 256;
        double s = 0.0;
        #pragma unroll
        for (int k = 0; k < 8; k++) s += (double)fc[l + 32 * k];
        #pragma unroll
        for (int o = 16; o > 0; o >>= 1) s += __shfl_xor_sync(0xFFFFFFFFu, s, o);
        if (l == 0) s_scd[b] = s;
    }
    __syncthreads();

    // ---- B phase: vertical 16-tall sliding sums -> C(dy,dx) = S_c + BoxSum, in place over H
    if (t < 66) {
        const int b = t / 33, dx = t - b * 33;
        float* hcol = s_h + (b * 48) * 33 + dx;
        double s = 0.0;
        #pragma unroll
        for (int y = 0; y < 16; y++) s += (double)hcol[y * 33];
        const double sc = s_scd[b];
        float prevC = (float)(sc + s);
        for (int dy = 1; dy <= 32; dy++) {
            s += (double)hcol[(dy + 15) * 33] - (double)hcol[(dy - 1) * 33];
            float cv = (float)(sc + s);
            hcol[(dy - 1) * 33] = prevC;   // overwrite H[dy-1]: consumed, never read again
            prevC = cv;
        }
        hcol[32 * 33] = prevC;
    }
    __syncthreads();

    const int u = (t < NITEMS) ? t : (NITEMS - 1);
    ull p = 0xFFFFFFFFFFFFFFFFULL;

    if (u < J8END) {
        // ---- j8 item: u = b*132 + g*33 + dyi ; dx = 8g + j, j in [0,8)
        const int b   = u / 132;
        const int v0  = u - b * 132;
        const int g   = v0 / 33;
        const int dyi = v0 - g * 33;
        const int colbase = b * BSZ + 8 * g;   // even -> 16B-aligned

        ull acc[8];
        #pragma unroll
        for (int j = 0; j < 8; j++) acc[j] = 0ULL;

        #pragma unroll 2
        for (int rp = 0; rp < 8; ++rp) {
            ull c2[16];
            const ulonglong2* cp = reinterpret_cast<const ulonglong2*>(&s_cur[b * 128 + rp * 16]);
            #pragma unroll
            for (int k = 0; k < 8; k++) { ulonglong2 w = cp[k]; c2[2*k] = w.x; c2[2*k+1] = w.y; }

            const int prow = rp * 2 + dyi;
            ull r2[24];   // need 23, load 24 aligned
            const ulonglong2* rr = reinterpret_cast<const ulonglong2*>(&s_ref[prow * RST + colbase]);
            #pragma unroll
            for (int k = 0; k < 12; k++) { ulonglong2 w = rr[k]; r2[2*k] = w.x; r2[2*k+1] = w.y; }

            #pragma unroll
            for (int j = 0; j < 8; j++) {
                ull a = acc[j];
                #pragma unroll
                for (int c = 0; c < 16; c++)
                    a = f2x_minadd(a, c2[c], r2[c + j]);
                acc[j] = a;
            }
        }
        const float* crow = s_h + (b * 48 + dyi) * 33 + 8 * g;
        #pragma unroll
        for (int j = 0; j < 8; j++) {
            float M2 = __uint_as_float((unsigned)(acc[j] & 0xFFFFFFFFu))
                     + __uint_as_float((unsigned)(acc[j] >> 32));
            float s = fmaxf(fmaf(-2.0f, M2, crow[j]), 0.0f);
            unsigned key = (unsigned)(dyi * 33 + 8 * g + j);
            p = umin64(p, ((ull)__float_as_uint(s) << 32) | (ull)key);
        }
    } else {
        // ---- j1 fixup item (dx = 32): u - J8END = b*33 + dyi
        const int v1  = u - J8END;
        const int b   = v1 / 33;
        const int dyi = v1 - b * 33;
        const int colbase = b * BSZ + 32;      // even

        ull acc = 0ULL;
        #pragma unroll 1
        for (int rp = 0; rp < 8; ++rp) {
            const int prow = rp * 2 + dyi;
            const ulonglong2* cp = reinterpret_cast<const ulonglong2*>(&s_cur[b * 128 + rp * 16]);
            const ulonglong2* rr = reinterpret_cast<const ulonglong2*>(&s_ref[prow * RST + colbase]);
            #pragma unroll
            for (int k = 0; k < 8; k++) {
                ulonglong2 cw = cp[k];
                ulonglong2 rw = rr[k];
                acc = f2x_minadd(acc, cw.x, rw.x);
                acc = f2x_minadd(acc, cw.y, rw.y);
            }
        }
        float M2 = __uint_as_float((unsigned)(acc & 0xFFFFFFFFu))
                 + __uint_as_float((unsigned)(acc >> 32));
        float s = fmaxf(fmaf(-2.0f, M2, s_h[(b * 48 + dyi) * 33 + 32]), 0.0f);
        unsigned key = (unsigned)(dyi * 33 + 32);
        p = ((ull)__float_as_uint(s) << 32) | (ull)key;
    }

    s_red[t] = p;
    __syncthreads();

    // ---- per-image-block reduction: warp rb reduces its block's 165 items
    if (t < 64) {
        const int rb = t >> 5;
        const int l  = t & 31;
        const int base = rb * 132;             // j8 items for this block
        ull best = s_red[base + l];
        best = umin64(best, s_red[base + l + 32]);
        best = umin64(best, s_red[base + l + 64]);
        best = umin64(best, s_red[base + l + 96]);
        if (l < 4)  best = umin64(best, s_red[base + l + 128]);
        const int base2 = J8END + rb * 33;     // j1 items
        if (l < 33 - 32) best = umin64(best, s_red[base2 + l + 32]);
        best = umin64(best, s_red[base2 + l]);
        #pragma unroll
        for (int o = 16; o > 0; o >>= 1) {
            ull q = __shfl_xor_sync(0xFFFFFFFFu, best, o);
            best = umin64(best, q);
        }
        if (l == 0) {
            unsigned key = (unsigned)(best & 0xFFFFFFFFu);
            int dyi_b = key / 33;
            int dxi_b = key - dyi_b * 33;
            int bg = by * NBX + cx * BPC + rb;
            out[bg]                 = (float)(dxi_b - SR);
            out[NBX * NBY + bg]     = (float)(dyi_b - SR);
            out[2 * NBX * NBY + bg] = __uint_as_float((unsigned)(best >> 32));
        }
    }
}

extern "C" void kernel_launch(void* const* d_in, const int* in_sizes, int n_in,
                              void* d_out, int out_size)
{
    const float* c  = (const float*)d_in[0];
    const float* r  = (const float*)d_in[1];
    float* out = (float*)d_out;
    dim3 grid(NBX / BPC, NBY);
    me_sad_kernel<<<grid, NTHREADS>>>(c, r, out);
}

// round 13
// speedup vs baseline: 1.9901x; 1.9901x over previous
#include <cuda_runtime.h>

#define BSZ 16
#define SR 16
#define IMW 2048
#define IMH 2048
#define NBX (IMW/BSZ)   // 128
#define NBY (IMH/BSZ)   // 128

#define BPC 2                   // image blocks per CTA (horizontal)
#define WINW (BPC*BSZ + 2*SR)   // 64
#define WINH (BSZ + 2*SR)       // 48
#define RST 66                  // ref row stride in pairs: 528 B -> conflict-free
#define NTHREADS 352            // 11 warps
#define J8END 264               // items [0,264): 2 blocks x 4 groups x 33 dy, NJ=8
#define NITEMS 330              // + 66 j1 items (dx=32): [264,330)

typedef unsigned long long ull;

__device__ __forceinline__ ull f2x_add(ull a, ull b) {
    ull d; asm("add.rn.f32x2 %0, %1, %2;" : "=l"(d) : "l"(a), "l"(b)); return d;
}
__device__ __forceinline__ ull umin64(ull a, ull b) { return b < a ? b : a; }

// acc += pack(min(a.lo,b.lo), min(a.hi,b.hi))
__device__ __forceinline__ ull f2x_minadd(ull acc, ull a, ull b) {
    float alo, ahi, blo, bhi;
    asm("mov.b64 {%0,%1}, %2;" : "=f"(alo), "=f"(ahi) : "l"(a));
    asm("mov.b64 {%0,%1}, %2;" : "=f"(blo), "=f"(bhi) : "l"(b));
    float m0 = fminf(alo, blo);
    float m1 = fminf(ahi, bhi);
    ull m; asm("mov.b64 %0, {%1,%2};" : "=l"(m) : "f"(m0), "f"(m1));
    return f2x_add(acc, m);
}

__global__ __launch_bounds__(NTHREADS, 3)
void me_sad_kernel(const float* __restrict__ cur,
                   const float* __restrict__ refF,
                   float* __restrict__ out)
{
    __shared__ __align__(16) ull s_ref[47 * RST];          // 24.8 KB row-pair window
    __shared__ __align__(16) ull s_cur[BPC * 8 * 16];      // 2 KB
    __shared__ ull s_red[NTHREADS];                        // 2.8 KB
    __shared__ float s_h[BPC * 48 * 33];                   // 12.7 KB: H sums, then C in place
    __shared__ float s_sc[BPC];

    const int t  = threadIdx.x;
    const int cx = blockIdx.x;          // 0..63
    const int by = blockIdx.y;          // 0..127
    const int gx0 = cx * (BPC * BSZ) - SR;
    const int gy0 = by * BSZ - SR;

    // ---- fill ref window (64x48): value feeds .lo of pair-row p and .hi of pair-row p-1
    float* fref = reinterpret_cast<float*>(s_ref);
    for (int i = t; i < WINW * WINH; i += NTHREADS) {
        int pr = i / WINW, pc = i - pr * WINW;
        int gy = gy0 + pr, gx = gx0 + pc;
        float v = 0.0f;
        if ((unsigned)gy < (unsigned)IMH && (unsigned)gx < (unsigned)IMW)
            v = refF[gy * IMW + gx];
        if (pr < WINH - 1) fref[(pr * RST + pc) * 2]           = v;
        if (pr >= 1)       fref[((pr - 1) * RST + pc) * 2 + 1] = v;
    }
    // ---- fill current blocks (2 x 16x16) as row-pairs
    float* fcur = reinterpret_cast<float*>(s_cur);
    for (int i = t; i < BPC * 256; i += NTHREADS) {
        int b = i >> 8;
        int r = (i >> 4) & 15, c = i & 15;
        float v = cur[(by * BSZ + r) * IMW + (cx * BPC + b) * BSZ + c];
        fcur[(b * 128 + (r >> 1) * 16 + c) * 2 + (r & 1)] = v;
    }
    __syncthreads();

    // ---- H phase (fp32, parallel): H[b][y][dx] = sum of 16 ref values in row y from col b*16+dx
    // 288 threads: (b, y, seg), seg covers 11 dx each; chain <= 36 FADDs
    if (t < 288) {
        const int b = t / 144, rem = t - b * 144;
        const int y = rem / 3, seg = rem - (rem / 3) * 3;
        const int dx0 = seg * 11;
        // raw ref value at (y,col): row y is .lo of pair y (y<47) or .hi of pair 46 (y==47)
        const float* rowp = (y < 47) ? (fref + y * RST * 2) : (fref + 46 * RST * 2 + 1);
        const int col0 = b * BSZ + dx0;
        float s = 0.0f;
        #pragma unroll
        for (int c = 0; c < 16; c++) s += rowp[(col0 + c) * 2];
        float* hrow = s_h + (b * 48 + y) * 33 + dx0;
        hrow[0] = s;
        #pragma unroll
        for (int k = 1; k < 11; k++) {
            s += rowp[(col0 + k + 15) * 2] - rowp[(col0 + k - 1) * 2];
            hrow[k] = s;
        }
    } else {
        // ---- S_c: per-block sum of current block (fp32, warp-parallel), threads 288..351
        const int b = (t - 288) >> 5, l = (t - 288) & 31;
        const float* fc = fcur + b * 256;
        float s = 0.0f;
        #pragma unroll
        for (int k = 0; k < 8; k++) s += fc[l + 32 * k];
        #pragma unroll
        for (int o = 16; o > 0; o >>= 1) s += __shfl_xor_sync(0xFFFFFFFFu, s, o);
        if (l == 0) s_sc[b] = s;
    }
    __syncthreads();

    // ---- B phase (fp32, parallel): C[b][dy][dx] = Sc + sum_{y=dy}^{dy+15} H[b][y][dx]
    // 198 threads: (b, dx, seg), seg covers 11 dy each; compute to regs, barrier, overwrite H
    float cvals[11];
    int cb = 0, cdx = 0, cdy0 = 0;
    if (t < 198) {
        cb = t / 99;
        const int rem = t - cb * 99;
        cdx = rem / 3;
        const int seg = rem - (rem / 3) * 3;
        cdy0 = seg * 11;
        const float* hcol = s_h + (cb * 48) * 33 + cdx;
        float s = 0.0f;
        #pragma unroll
        for (int y = 0; y < 16; y++) s += hcol[(cdy0 + y) * 33];
        const float sc = s_sc[cb];
        cvals[0] = sc + s;
        #pragma unroll
        for (int k = 1; k < 11; k++) {
            s += hcol[(cdy0 + k + 15) * 33] - hcol[(cdy0 + k - 1) * 33];
            cvals[k] = sc + s;
        }
    }
    __syncthreads();
    if (t < 198) {
        float* ccol = s_h + (cb * 48) * 33 + cdx;
        #pragma unroll
        for (int k = 0; k < 11; k++) ccol[(cdy0 + k) * 33] = cvals[k];
    }
    __syncthreads();

    const int u = (t < NITEMS) ? t : (NITEMS - 1);
    ull p = 0xFFFFFFFFFFFFFFFFULL;

    if (u < J8END) {
        // ---- j8 item: u = b*132 + g*33 + dyi ; dx = 8g + j, j in [0,8)
        const int b   = u / 132;
        const int v0  = u - b * 132;
        const int g   = v0 / 33;
        const int dyi = v0 - g * 33;
        const int colbase = b * BSZ + 8 * g;   // even -> 16B-aligned

        ull acc[8];
        #pragma unroll
        for (int j = 0; j < 8; j++) acc[j] = 0ULL;

        #pragma unroll 2
        for (int rp = 0; rp < 8; ++rp) {
            ull c2[16];
            const ulonglong2* cp = reinterpret_cast<const ulonglong2*>(&s_cur[b * 128 + rp * 16]);
            #pragma unroll
            for (int k = 0; k < 8; k++) { ulonglong2 w = cp[k]; c2[2*k] = w.x; c2[2*k+1] = w.y; }

            const int prow = rp * 2 + dyi;
            ull r2[24];   // need 23, load 24 aligned
            const ulonglong2* rr = reinterpret_cast<const ulonglong2*>(&s_ref[prow * RST + colbase]);
            #pragma unroll
            for (int k = 0; k < 12; k++) { ulonglong2 w = rr[k]; r2[2*k] = w.x; r2[2*k+1] = w.y; }

            #pragma unroll
            for (int j = 0; j < 8; j++) {
                ull a = acc[j];
                #pragma unroll
                for (int c = 0; c < 16; c++)
                    a = f2x_minadd(a, c2[c], r2[c + j]);
                acc[j] = a;
            }
        }
        const float* crow = s_h + (b * 48 + dyi) * 33 + 8 * g;
        #pragma unroll
        for (int j = 0; j < 8; j++) {
            float M2 = __uint_as_float((unsigned)(acc[j] & 0xFFFFFFFFu))
                     + __uint_as_float((unsigned)(acc[j] >> 32));
            float s = fmaxf(fmaf(-2.0f, M2, crow[j]), 0.0f);
            unsigned key = (unsigned)(dyi * 33 + 8 * g + j);
            p = umin64(p, ((ull)__float_as_uint(s) << 32) | (ull)key);
        }
    } else {
        // ---- j1 fixup item (dx = 32): u - J8END = b*33 + dyi
        const int v1  = u - J8END;
        const int b   = v1 / 33;
        const int dyi = v1 - b * 33;
        const int colbase = b * BSZ + 32;      // even

        ull acc = 0ULL;
        #pragma unroll 1
        for (int rp = 0; rp < 8; ++rp) {
            const int prow = rp * 2 + dyi;
            const ulonglong2* cp = reinterpret_cast<const ulonglong2*>(&s_cur[b * 128 + rp * 16]);
            const ulonglong2* rr = reinterpret_cast<const ulonglong2*>(&s_ref[prow * RST + colbase]);
            #pragma unroll
            for (int k = 0; k < 8; k++) {
                ulonglong2 cw = cp[k];
                ulonglong2 rw = rr[k];
                acc = f2x_minadd(acc, cw.x, rw.x);
                acc = f2x_minadd(acc, cw.y, rw.y);
            }
        }
        float M2 = __uint_as_float((unsigned)(acc & 0xFFFFFFFFu))
                 + __uint_as_float((unsigned)(acc >> 32));
        float s = fmaxf(fmaf(-2.0f, M2, s_h[(b * 48 + dyi) * 33 + 32]), 0.0f);
        unsigned key = (unsigned)(dyi * 33 + 32);
        p = ((ull)__float_as_uint(s) << 32) | (ull)key;
    }

    s_red[t] = p;
    __syncthreads();

    // ---- per-image-block reduction: warp rb reduces its block's 165 items
    if (t < 64) {
        const int rb = t >> 5;
        const int l  = t & 31;
        const int base = rb * 132;             // j8 items for this block
        ull best = s_red[base + l];
        best = umin64(best, s_red[base + l + 32]);
        best = umin64(best, s_red[base + l + 64]);
        best = umin64(best, s_red[base + l + 96]);
        if (l < 4)  best = umin64(best, s_red[base + l + 128]);
        const int base2 = J8END + rb * 33;     // j1 items
        if (l < 33 - 32) best = umin64(best, s_red[base2 + l + 32]);
        best = umin64(best, s_red[base2 + l]);
        #pragma unroll
        for (int o = 16; o > 0; o >>= 1) {
            ull q = __shfl_xor_sync(0xFFFFFFFFu, best, o);
            best = umin64(best, q);
        }
        if (l == 0) {
            unsigned key = (unsigned)(best & 0xFFFFFFFFu);
            int dyi_b = key / 33;
            int dxi_b = key - dyi_b * 33;
            int bg = by * NBX + cx * BPC + rb;
            out[bg]                 = (float)(dxi_b - SR);
            out[NBX * NBY + bg]     = (float)(dyi_b - SR);
            out[2 * NBX * NBY + bg] = __uint_as_float((unsigned)(best >> 32));
        }
    }
}

extern "C" void kernel_launch(void* const* d_in, const int* in_sizes, int n_in,
                              void* d_out, int out_size)
{
    const float* c  = (const float*)d_in[0];
    const float* r  = (const float*)d_in[1];
    float* out = (float*)d_out;
    dim3 grid(NBX / BPC, NBY);
    me_sad_kernel<<<grid, NTHREADS>>>(c, r, out);
}

// round 14
// speedup vs baseline: 2.0168x; 1.0135x over previous
#include <cuda_runtime.h>

#define BSZ 16
#define SR 16
#define IMW 2048
#define IMH 2048
#define NBX (IMW/BSZ)   // 128
#define NBY (IMH/BSZ)   // 128

#define BPC 4                   // image blocks per CTA (horizontal)
#define WINW (BPC*BSZ + 2*SR)   // 96
#define WINH (BSZ + 2*SR)       // 48
#define RST 98                  // even -> 16B-aligned pairs; 784 % 128 == 16 (conflict-free)
#define NTHREADS 608            // 19 warps
#define NJ8 528                 // 4 blocks x 4 groups x 33 dy
#define NJ1 132                 // 4 blocks x 33 dy (dx = 32)
#define J1THREADS 80            // threads 528..607 each handle up to 2 j1 items

typedef unsigned long long ull;

__device__ __forceinline__ ull f2x_sub(ull a, ull b) {
    ull d; asm("sub.rn.f32x2 %0, %1, %2;" : "=l"(d) : "l"(a), "l"(b)); return d;
}
__device__ __forceinline__ ull f2x_add(ull a, ull b) {
    ull d; asm("add.rn.f32x2 %0, %1, %2;" : "=l"(d) : "l"(a), "l"(b)); return d;
}
__device__ __forceinline__ ull f2x_abs(ull a) {
    return a & 0x7FFFFFFF7FFFFFFFULL;
}
__device__ __forceinline__ ull umin64(ull a, ull b) { return b < a ? b : a; }

__device__ __forceinline__ ull sad_pack(ull acc, int key) {
    float lo = __uint_as_float((unsigned)(acc & 0xFFFFFFFFu));
    float hi = __uint_as_float((unsigned)(acc >> 32));
    float s = lo + hi;
    return ((ull)__float_as_uint(s) << 32) | (ull)(unsigned)key;
}

// one j1 item (dx = 32) for (b, dyi); returns packed candidate
__device__ __forceinline__ ull j1_item(const ull* s_cur, const ull* s_ref, int b, int dyi) {
    const int colbase = b * BSZ + 32;   // even
    ull acc = 0ULL;
    #pragma unroll 1
    for (int rp = 0; rp < 8; ++rp) {
        const int prow = rp * 2 + dyi;
        const ulonglong2* cp = reinterpret_cast<const ulonglong2*>(&s_cur[b * 128 + rp * 16]);
        const ulonglong2* rr = reinterpret_cast<const ulonglong2*>(&s_ref[prow * RST + colbase]);
        #pragma unroll
        for (int k = 0; k < 8; k++) {
            ulonglong2 cw = cp[k];
            ulonglong2 rw = rr[k];
            acc = f2x_add(acc, f2x_abs(f2x_sub(cw.x, rw.x)));
            acc = f2x_add(acc, f2x_abs(f2x_sub(cw.y, rw.y)));
        }
    }
    return sad_pack(acc, dyi * 33 + 32);
}

__global__ __launch_bounds__(NTHREADS, 2)   // reg cap 53; 2 CTAs/SM = 38 warps
void me_sad_kernel(const float* __restrict__ cur,
                   const float* __restrict__ refF,
                   float* __restrict__ out)
{
    __shared__ __align__(16) ull s_ref[47 * RST];          // 36.0 KB row-pair window
    __shared__ __align__(16) ull s_cur[BPC * 8 * 16];      // 4 KB
    __shared__ ull s_red[NJ8 + NJ1];                       // 5.2 KB (per-item results)

    const int t  = threadIdx.x;
    const int cx = blockIdx.x;          // 0..31
    const int by = blockIdx.y;          // 0..127
    const int gx0 = cx * (BPC * BSZ) - SR;
    const int gy0 = by * BSZ - SR;

    // ---- fill ref window (96x48): value feeds .lo of pair-row p and .hi of pair-row p-1
    float* fref = reinterpret_cast<float*>(s_ref);
    for (int i = t; i < WINW * WINH; i += NTHREADS) {
        int pr = i / WINW, pc = i - pr * WINW;
        int gy = gy0 + pr, gx = gx0 + pc;
        float v = 0.0f;
        if ((unsigned)gy < (unsigned)IMH && (unsigned)gx < (unsigned)IMW)
            v = refF[gy * IMW + gx];
        if (pr < WINH - 1) fref[(pr * RST + pc) * 2]           = v;
        if (pr >= 1)       fref[((pr - 1) * RST + pc) * 2 + 1] = v;
    }
    // ---- fill current blocks (4 x 16x16) as row-pairs
    float* fcur = reinterpret_cast<float*>(s_cur);
    for (int i = t; i < BPC * 256; i += NTHREADS) {
        int b = i >> 8;
        int r = (i >> 4) & 15, c = i & 15;
        float v = cur[(by * BSZ + r) * IMW + (cx * BPC + b) * BSZ + c];
        fcur[(b * 128 + (r >> 1) * 16 + c) * 2 + (r & 1)] = v;
    }
    __syncthreads();

    if (t < NJ8) {
        // ---- j8 item: u = b*132 + g*33 + dyi ; dx = 8g + j, j in [0,8)
        const int u   = t;
        const int b   = u / 132;
        const int v0  = u - b * 132;
        const int g   = v0 / 33;
        const int dyi = v0 - g * 33;
        const int colbase = b * BSZ + 8 * g;   // even -> 16B-aligned

        ull acc[8];
        #pragma unroll
        for (int j = 0; j < 8; j++) acc[j] = 0ULL;

        #pragma unroll 2
        for (int rp = 0; rp < 8; ++rp) {
            ull c2[16];
            const ulonglong2* cp = reinterpret_cast<const ulonglong2*>(&s_cur[b * 128 + rp * 16]);
            #pragma unroll
            for (int k = 0; k < 8; k++) { ulonglong2 w = cp[k]; c2[2*k] = w.x; c2[2*k+1] = w.y; }

            const int prow = rp * 2 + dyi;
            ull r2[24];   // need 23, load 24 aligned
            const ulonglong2* rr = reinterpret_cast<const ulonglong2*>(&s_ref[prow * RST + colbase]);
            #pragma unroll
            for (int k = 0; k < 12; k++) { ulonglong2 w = rr[k]; r2[2*k] = w.x; r2[2*k+1] = w.y; }

            #pragma unroll
            for (int j = 0; j < 8; j++) {
                ull a = acc[j];
                #pragma unroll
                for (int c = 0; c < 16; c++)
                    a = f2x_add(a, f2x_abs(f2x_sub(c2[c], r2[c + j])));
                acc[j] = a;
            }
        }
        ull p = 0xFFFFFFFFFFFFFFFFULL;
        #pragma unroll
        for (int j = 0; j < 8; j++)
            p = umin64(p, sad_pack(acc[j], dyi * 33 + 8 * g + j));
        s_red[t] = p;
    } else {
        // ---- j1 threads: each covers items idx0 and idx0+80 (dx = 32)
        const int idx0 = t - NJ8;                  // 0..79
        {
            const int b = idx0 / 33, dyi = idx0 - b * 33;
            s_red[NJ8 + idx0] = j1_item(s_cur, s_ref, b, dyi);
        }
        const int idx1 = idx0 + J1THREADS;         // 80..159
        if (idx1 < NJ1) {
            const int b = idx1 / 33, dyi = idx1 - b * 33;
            s_red[NJ8 + idx1] = j1_item(s_cur, s_ref, b, dyi);
        }
    }
    __syncthreads();

    // ---- per-image-block reduction: warp rb (rb<4) reduces its block's 165 items
    if (t < 128) {
        const int rb = t >> 5;
        const int l  = t & 31;
        const int base = rb * 132;                 // j8 items
        ull best = s_red[base + l];
        best = umin64(best, s_red[base + l + 32]);
        best = umin64(best, s_red[base + l + 64]);
        best = umin64(best, s_red[base + l + 96]);
        if (l < 4)  best = umin64(best, s_red[base + l + 128]);
        const int base2 = NJ8 + rb * 33;           // j1 items
        best = umin64(best, s_red[base2 + l]);
        if (l == 0) best = umin64(best, s_red[base2 + 32]);
        #pragma unroll
        for (int o = 16; o > 0; o >>= 1) {
            ull q = __shfl_xor_sync(0xFFFFFFFFu, best, o);
            best = umin64(best, q);
        }
        if (l == 0) {
            unsigned key = (unsigned)(best & 0xFFFFFFFFu);
            int dyi_b = key / 33;
            int dxi_b = key - dyi_b * 33;
            int bg = by * NBX + cx * BPC + rb;
            out[bg]                 = (float)(dxi_b - SR);
            out[NBX * NBY + bg]     = (float)(dyi_b - SR);
            out[2 * NBX * NBY + bg] = __uint_as_float((unsigned)(best >> 32));
        }
    }
}

extern "C" void kernel_launch(void* const* d_in, const int* in_sizes, int n_in,
                              void* d_out, int out_size)
{
    const float* c  = (const float*)d_in[0];
    const float* r  = (const float*)d_in[1];
    float* out = (float*)d_out;
    dim3 grid(NBX / BPC, NBY);
    me_sad_kernel<<<grid, NTHREADS>>>(c, r, out);
}